// round 9
// baseline (speedup 1.0000x reference)
#include <cuda_runtime.h>
#include <cuda_bf16.h>
#include <cstdint>

typedef unsigned long long ull;
#define FULL 0xffffffffu

constexpr int B_  = 16;
constexpr int N_  = 4096;
constexpr int NP_ = 1024;
constexpr int K_  = 32;
constexpr int CIN = 128;
constexpr int CG  = 131;   // 3 + 128
constexpr int C_  = 256;
constexpr int H_  = 4;
constexpr int D_  = 64;
constexpr int TC  = 768;   // 3*C
constexpr int G_  = 2;     // groups per attn block (M = 64 rows)
constexpr int GP  = 34;    // per-group sub-pitch (floats) in xsT row
constexpr int XP  = 70;    // xsT row pitch (floats)
constexpr int T_  = 256;   // attn threads
constexpr int RPB = 16;    // rows per block in mlp kernel
constexpr int KC  = 48;    // K-chunk for mma (3 chunks: 144 >= 131, zero pad)
constexpr int AP  = 26;    // A/B smem row pitch in 32-bit words

// scratch (device globals: allocation-free rule)
__device__ int   g_idx_buf[B_ * NP_ * K_];
__device__ float g_feat_buf[B_ * NP_ * C_];
// Wq as bf16 hi/lo, [chunk][part][n=256][24 words of k-pairs]
__device__ __align__(16) unsigned g_wq[3 * 2 * 256 * 24];

extern __shared__ __align__(16) unsigned char dynsm[];

// ---------------- packed f32x2 helpers
__device__ __forceinline__ ull pk2(float a, float b) {
    ull r;
    asm("mov.b64 %0, {%1,%2};" : "=l"(r) : "f"(a), "f"(b));
    return r;
}
__device__ __forceinline__ void upk2(ull v, float& a, float& b) {
    asm("mov.b64 {%0,%1}, %2;" : "=f"(a), "=f"(b) : "l"(v));
}
__device__ __forceinline__ void fma2(ull& d, ull a, ull b) {
    asm("fma.rn.f32x2 %0, %1, %2, %3;" : "=l"(d) : "l"(a), "l"(b), "l"(d));
}

// ---------------- warp mma m16n8k16 bf16 (base PTX, works at compute_103)
__device__ __forceinline__ void mma16816(float* d, const unsigned* a, unsigned b0, unsigned b1) {
    asm volatile(
        "mma.sync.aligned.m16n8k16.row.col.f32.bf16.bf16.f32 "
        "{%0,%1,%2,%3}, {%4,%5,%6,%7}, {%8,%9}, {%0,%1,%2,%3};"
        : "+f"(d[0]), "+f"(d[1]), "+f"(d[2]), "+f"(d[3])
        : "r"(a[0]), "r"(a[1]), "r"(a[2]), "r"(a[3]), "r"(b0), "r"(b1));
}
__device__ __forceinline__ unsigned bf16pair(float x0, float x1) {
    const __nv_bfloat16 h0 = __float2bfloat16(x0), h1 = __float2bfloat16(x1);
    return (unsigned)__bfloat16_as_ushort(h0) | ((unsigned)__bfloat16_as_ushort(h1) << 16);
}

// ============================================================================
// K0: prep — Wq (131x256 fp32, k-major rows) -> bf16 hi/lo, [c][part][n][24w],
// k padded to 144 with zeros.
// ============================================================================
__global__ void __launch_bounds__(512) prep_kernel(const float* __restrict__ wqkv) {
    const int idx = blockIdx.x * 512 + threadIdx.x;
    if (idx >= 3 * 256 * 24) return;
    const int c = idx / 6144;
    const int rem = idx % 6144;
    const int n = rem / 24, j = rem % 24;
    const int k = c * KC + 2 * j;
    const float x0 = (k < CG) ? wqkv[(long)k * TC + n] : 0.f;
    const float x1 = (k + 1 < CG) ? wqkv[(long)(k + 1) * TC + n] : 0.f;
    const __nv_bfloat16 h0 = __float2bfloat16(x0), h1 = __float2bfloat16(x1);
    const float r0 = x0 - __bfloat162float(h0), r1 = x1 - __bfloat162float(h1);
    g_wq[(c * 2 + 0) * 6144 + n * 24 + j] = bf16pair(x0, x1);   // hi
    g_wq[(c * 2 + 1) * 6144 + n * 24 + j] = bf16pair(r0, r1);   // lo
}

// ============================================================================
// K1: KNN. One warp per query, max-replacement top-32 (set-only).
// ============================================================================
__global__ void __launch_bounds__(256) knn_kernel(const float* __restrict__ xyz,
                                                  const float* __restrict__ nxyz) {
    float4* pts = reinterpret_cast<float4*>(dynsm);
    const int b = blockIdx.y;
    const float* xb = xyz + (long)b * N_ * 3;
    for (int j = threadIdx.x; j < N_; j += 256) {
        float x = xb[j * 3 + 0], y = xb[j * 3 + 1], z = xb[j * 3 + 2];
        pts[j] = make_float4(x, y, z, x * x + y * y + z * z);
    }
    __syncthreads();

    const int warp = threadIdx.x >> 5, lane = threadIdx.x & 31;
    const int p = blockIdx.x * 8 + warp;
    const float* q = nxyz + ((long)b * NP_ + p) * 3;
    const float qx = q[0], qy = q[1], qz = q[2];

    float4 c0 = pts[lane];
    float bestd = c0.w - 2.f * (qx * c0.x + qy * c0.y + qz * c0.z);
    int besti = lane;

    float curmax = bestd;
#pragma unroll
    for (int o = 16; o; o >>= 1) curmax = fmaxf(curmax, __shfl_xor_sync(FULL, curmax, o));

    for (int j0 = K_; j0 < N_; j0 += K_) {
        float4 c = pts[j0 + lane];
        float d = c.w - 2.f * (qx * c.x + qy * c.y + qz * c.z);
        unsigned mset = __ballot_sync(FULL, d < curmax);
        while (mset) {
            int src = __ffs(mset) - 1;
            mset &= mset - 1;
            float cd = __shfl_sync(FULL, d, src);
            if (cd < curmax) {
                unsigned vict = __ballot_sync(FULL, bestd == curmax);
                int vl = __ffs(vict) - 1;
                if (lane == vl) { bestd = cd; besti = j0 + src; }
                float v = bestd;
#pragma unroll
                for (int o = 16; o; o >>= 1) v = fmaxf(v, __shfl_xor_sync(FULL, v, o));
                curmax = v;
            }
        }
    }
    g_idx_buf[((long)b * NP_ + p) * K_ + lane] = besti;
}

// ============================================================================
// K2: fused group -> LN -> Q GEMM (mma.sync bf16 split) -> collapsed K/V
// attention -> proj+dense. G=2 (M=64) and B single-part passes so smem ~90KB
// -> 2 blocks/SM (occupancy was the round-8 binder).
// ============================================================================
struct __align__(16) SmemAll {
    unsigned Abf[2][64][AP];    // x bf16 hi/lo, one 48-K chunk      (13.3 KB)
    unsigned Bbf[256][AP];      // Wq bf16, ONE part of one chunk    (26.6 KB)
    float xsT[CG][XP];          // LN'd grouped features, transposed (36.7 KB)
    float pad0[2];
    float qm[G_][C_];
    float gmax[G_][132];
    float z[G_][H_][132];
    float y[G_][H_][132];
    float attnw[G_][H_][K_];
    float sat[G_][C_];
    int   nidx[G_][K_];
    float q3[G_][4];
};

__global__ void __launch_bounds__(T_, 2) attn_kernel(
    const float* __restrict__ xyz, const float* __restrict__ nxyz,
    const float* __restrict__ featin, const float* __restrict__ wqkv,
    const float* __restrict__ projw, const float* __restrict__ projb,
    const float* __restrict__ densew, const float* __restrict__ denseb,
    const float* __restrict__ n1g, const float* __restrict__ n1b) {
    SmemAll& s = *reinterpret_cast<SmemAll*>(dynsm);
    const int t = threadIdx.x;
    const int w = t >> 5, lane = t & 31;
    const int grp0 = blockIdx.x * G_;
    const int b = grp0 >> 10, p0 = grp0 & 1023;

    if (t < G_ * K_) {
        int g = t >> 5, r = t & 31;
        s.nidx[g][r] = g_idx_buf[(long)(grp0 + g) * K_ + r];
    }
    if (t < G_ * 3) {
        int g = t / 3, c = t % 3;
        s.q3[g][c] = nxyz[((long)b * NP_ + p0 + g) * 3 + c];
    }
    __syncthreads();

    // gather: relative xyz (rows 0..2) + features (rows 3..130)
    if (t < G_ * K_) {
        int g = t >> 5, r = t & 31;
        int j = s.nidx[g][r];
        const float* xp = xyz + ((long)b * N_ + j) * 3;
        s.xsT[0][g * GP + r] = xp[0] - s.q3[g][0];
        s.xsT[1][g * GP + r] = xp[1] - s.q3[g][1];
        s.xsT[2][g * GP + r] = xp[2] - s.q3[g][2];
    }
    for (int e = t; e < G_ * K_ * CIN; e += T_) {
        int g = e >> 12, r = (e >> 7) & 31, i = e & 127;
        s.xsT[3 + i][g * GP + r] = featin[((long)b * N_ + s.nidx[g][r]) * CIN + i];
    }
    __syncthreads();

    // max over K of raw gf (dense branch) before LN overwrites
    for (int e = t; e < G_ * CG; e += T_) {
        int g = e / CG, i = e - g * CG;
        float m = s.xsT[i][g * GP];
#pragma unroll
        for (int r = 1; r < K_; ++r) m = fmaxf(m, s.xsT[i][g * GP + r]);
        s.gmax[g][i] = m;
    }
    __syncthreads();

    // LayerNorm over CG=131 per row; warp w (0..7) owns rows w+8k
    for (int k = 0; k < 8; ++k) {
        const int row = w + 8 * k;
        const int g = row >> 5, r = row & 31;
        float v[5];
        int kn = 0;
        float sum = 0.f;
        for (int ii = lane; ii < CG; ii += 32) { v[kn] = s.xsT[ii][g * GP + r]; sum += v[kn]; ++kn; }
#pragma unroll
        for (int o = 16; o; o >>= 1) sum += __shfl_xor_sync(FULL, sum, o);
        const float m = sum * (1.f / CG);
        float qv = 0.f;
        for (int kk = 0; kk < kn; ++kk) { float d = v[kk] - m; qv += d * d; }
#pragma unroll
        for (int o = 16; o; o >>= 1) qv += __shfl_xor_sync(FULL, qv, o);
        const float rs = rsqrtf(qv * (1.f / CG) + 1e-3f);
        kn = 0;
        for (int ii = lane; ii < CG; ii += 32) {
            s.xsT[ii][g * GP + r] = (v[kn] - m) * rs * n1g[ii] + n1b[ii];
            ++kn;
        }
    }
    __syncthreads();

    // ================= Q GEMM on tensor cores (mma.sync, split bf16) ========
    // warp w (0..7): group gq = w&1 (rows 32gq..32gq+31), n-cols (w>>1)*64..+63
    const int gq = w & 1;
    const int mbase = 32 * gq;
    const int nbase = (w >> 1) * 64;
    const int lp = lane >> 2, lq = lane & 3;
    float cfr[2][8][4];
#pragma unroll
    for (int mt = 0; mt < 2; ++mt)
#pragma unroll
        for (int j = 0; j < 8; ++j)
#pragma unroll
            for (int e = 0; e < 4; ++e) cfr[mt][j][e] = 0.f;

    const unsigned* A0 = &s.Abf[0][0][0];
    const unsigned* A1 = &s.Abf[1][0][0];
    const unsigned* BB = &s.Bbf[0][0];

    for (int c = 0; c < 3; ++c) {
        // --- convert A chunk c: xsT fp32 -> bf16 hi/lo pairs (both parts)
        for (int e = t; e < 64 * 24; e += T_) {
            const int m = e / 24, j = e % 24;
            const int colx = (m >> 5) * GP + (m & 31);
            const int k = c * KC + 2 * j;
            const float x0 = (k < CG) ? s.xsT[k][colx] : 0.f;
            const float x1 = (k + 1 < CG) ? s.xsT[k + 1][colx] : 0.f;
            const __nv_bfloat16 h0 = __float2bfloat16(x0), h1 = __float2bfloat16(x1);
            s.Abf[0][m][j] = (unsigned)__bfloat16_as_ushort(h0) |
                             ((unsigned)__bfloat16_as_ushort(h1) << 16);
            s.Abf[1][m][j] = bf16pair(x0 - __bfloat162float(h0), x1 - __bfloat162float(h1));
        }
        // --- copy B chunk c part HI (re-pitch 24 -> 26 words)
        {
            const uint2* src = reinterpret_cast<const uint2*>(g_wq) + (long)(c * 2) * 3072;
            uint2* dst = reinterpret_cast<uint2*>(&s.Bbf[0][0]);
            for (int i = t; i < 3072; i += T_) {
                const int row = i / 12, j2 = i % 12;
                dst[row * 13 + j2] = src[i];
            }
        }
        __syncthreads();

        // --- pass 1: hh + lh against B_hi
#pragma unroll
        for (int ks = 0; ks < 3; ++ks) {
            const int ko = ks * 8 + lq;
            unsigned ah[2][4], al[2][4];
#pragma unroll
            for (int mt = 0; mt < 2; ++mt) {
                const int r0 = (mbase + mt * 16 + lp) * AP;
                const int r8 = r0 + 8 * AP;
                ah[mt][0] = A0[r0 + ko];     ah[mt][1] = A0[r8 + ko];
                ah[mt][2] = A0[r0 + ko + 4]; ah[mt][3] = A0[r8 + ko + 4];
                al[mt][0] = A1[r0 + ko];     al[mt][1] = A1[r8 + ko];
                al[mt][2] = A1[r0 + ko + 4]; al[mt][3] = A1[r8 + ko + 4];
            }
#pragma unroll
            for (int j = 0; j < 8; ++j) {
                const int nr = (nbase + j * 8 + lp) * AP;
                const unsigned b0 = BB[nr + ko], b1 = BB[nr + ko + 4];
#pragma unroll
                for (int mt = 0; mt < 2; ++mt) {
                    mma16816(cfr[mt][j], ah[mt], b0, b1);
                    mma16816(cfr[mt][j], al[mt], b0, b1);
                }
            }
        }
        __syncthreads();

        // --- copy B chunk c part LO
        {
            const uint2* src = reinterpret_cast<const uint2*>(g_wq) + (long)(c * 2 + 1) * 3072;
            uint2* dst = reinterpret_cast<uint2*>(&s.Bbf[0][0]);
            for (int i = t; i < 3072; i += T_) {
                const int row = i / 12, j2 = i % 12;
                dst[row * 13 + j2] = src[i];
            }
        }
        __syncthreads();

        // --- pass 2: hl against B_lo
#pragma unroll
        for (int ks = 0; ks < 3; ++ks) {
            const int ko = ks * 8 + lq;
            unsigned ah[2][4];
#pragma unroll
            for (int mt = 0; mt < 2; ++mt) {
                const int r0 = (mbase + mt * 16 + lp) * AP;
                const int r8 = r0 + 8 * AP;
                ah[mt][0] = A0[r0 + ko];     ah[mt][1] = A0[r8 + ko];
                ah[mt][2] = A0[r0 + ko + 4]; ah[mt][3] = A0[r8 + ko + 4];
            }
#pragma unroll
            for (int j = 0; j < 8; ++j) {
                const int nr = (nbase + j * 8 + lp) * AP;
                const unsigned b0 = BB[nr + ko], b1 = BB[nr + ko + 4];
#pragma unroll
                for (int mt = 0; mt < 2; ++mt)
                    mma16816(cfr[mt][j], ah[mt], b0, b1);
            }
        }
        __syncthreads();
    }

    // per-group column max from C fragments
#pragma unroll
    for (int j = 0; j < 8; ++j) {
        float ve = fmaxf(fmaxf(cfr[0][j][0], cfr[0][j][2]), fmaxf(cfr[1][j][0], cfr[1][j][2]));
        float vo = fmaxf(fmaxf(cfr[0][j][1], cfr[0][j][3]), fmaxf(cfr[1][j][1], cfr[1][j][3]));
#pragma unroll
        for (int o = 4; o <= 16; o <<= 1) {
            ve = fmaxf(ve, __shfl_xor_sync(FULL, ve, o));
            vo = fmaxf(vo, __shfl_xor_sync(FULL, vo, o));
        }
        if (lane < 4) {
            s.qm[gq][nbase + j * 8 + 2 * lane]     = ve;
            s.qm[gq][nbase + j * 8 + 2 * lane + 1] = vo;
        }
    }
    __syncthreads();

    // ---- z[g][h][i] = sum_d qm[g][h*64+d] * Wk[i][h*64+d]; warp-per-i
    {
        float4 qa[G_], qb[G_];
#pragma unroll
        for (int g = 0; g < G_; ++g) {
            qa[g] = reinterpret_cast<const float4*>(s.qm[g])[lane];
            qb[g] = reinterpret_cast<const float4*>(s.qm[g])[32 + lane];
        }
        for (int i = w; i < CG; i += 8) {
            const float4* wr = reinterpret_cast<const float4*>(wqkv + (long)i * TC + C_);
            const float4 w0 = wr[lane];
            const float4 w1 = wr[32 + lane];
            float s0[G_], s1[G_];
#pragma unroll
            for (int g = 0; g < G_; ++g) {
                s0[g] = w0.x * qa[g].x + w0.y * qa[g].y + w0.z * qa[g].z + w0.w * qa[g].w;
                s1[g] = w1.x * qb[g].x + w1.y * qb[g].y + w1.z * qb[g].z + w1.w * qb[g].w;
            }
#pragma unroll
            for (int o = 8; o; o >>= 1) {
#pragma unroll
                for (int g = 0; g < G_; ++g) {
                    s0[g] += __shfl_xor_sync(FULL, s0[g], o);
                    s1[g] += __shfl_xor_sync(FULL, s1[g], o);
                }
            }
            if ((lane & 15) == 0) {
                const int h0 = lane >> 4;
#pragma unroll
                for (int g = 0; g < G_; ++g) {
                    s.z[g][h0][i]     = s0[g];
                    s.z[g][h0 + 2][i] = s1[g];
                }
            }
        }
    }
    __syncthreads();

    // ---- logits + softmax: warp w = (g,h), lane = row r (8 warps exactly)
    {
        const int g = w >> 2, h = w & 3, r = lane;
        float a = 0.f;
#pragma unroll 4
        for (int i = 0; i < CG; ++i) a += s.xsT[i][g * GP + r] * s.z[g][h][i];
        a *= 0.0625f;
        float mx = a;
#pragma unroll
        for (int o = 16; o; o >>= 1) mx = fmaxf(mx, __shfl_xor_sync(FULL, mx, o));
        const float e = expf(a - mx);
        float ss = e;
#pragma unroll
        for (int o = 16; o; o >>= 1) ss += __shfl_xor_sync(FULL, ss, o);
        s.attnw[g][h][r] = e / ss;
    }
    __syncthreads();

    // ---- y[g][h][i] = sum_r attnw[g][h][r] * x[i][r]
    for (int e = t; e < G_ * H_ * CG; e += T_) {
        const int i = e % CG;
        const int gh = e / CG;
        const int g = gh >> 2, h = gh & 3;
        const ull* aw = reinterpret_cast<const ull*>(s.attnw[g][h]);
        const ull* xr = reinterpret_cast<const ull*>(&s.xsT[i][g * GP]);
        ull acc = 0ull;
#pragma unroll
        for (int rp = 0; rp < 16; ++rp) fma2(acc, xr[rp], aw[rp]);
        float a, b2; upk2(acc, a, b2);
        s.y[g][h][i] = a + b2;
    }
    __syncthreads();

    // ---- sat[g][c] = sum_i y[g][h][i] * Wv[i][c]; thread = c, both groups
    {
        const int c = t;
        const int h = c >> 6;
        const float* wv = wqkv + 2 * C_ + c;
        float a0 = 0.f, a1 = 0.f;
#pragma unroll 8
        for (int i = 0; i < CG; ++i) {
            const float wvi = wv[(long)i * TC];
            a0 += s.y[0][h][i] * wvi;
            a1 += s.y[1][h][i] * wvi;
        }
        s.sat[0][c] = a0;
        s.sat[1][c] = a1;
    }
    __syncthreads();

    // ---- proj (relu) + dense (relu): thread = c, both groups
    {
        const int c = t;
        float p0 = 0.f, p1 = 0.f;
        const float* wp = projw + c;
#pragma unroll 8
        for (int i = 0; i < C_; ++i) {
            const float wv = wp[(long)i * C_];
            p0 += s.sat[0][i] * wv;
            p1 += s.sat[1][i] * wv;
        }
        float d0 = 0.f, d1 = 0.f;
        const float* wd = densew + c;
#pragma unroll 8
        for (int i = 0; i < CG; ++i) {
            const float wv = wd[(long)i * C_];
            d0 += s.gmax[0][i] * wv;
            d1 += s.gmax[1][i] * wv;
        }
        const float pb = projb[c], db = denseb[c];
        g_feat_buf[(long)(grp0 + 0) * C_ + c] = fmaxf(p0 + pb, 0.f) + fmaxf(d0 + db, 0.f);
        g_feat_buf[(long)(grp0 + 1) * C_ + c] = fmaxf(p1 + pb, 0.f) + fmaxf(d1 + db, 0.f);
    }
}

// ============================================================================
// K3: LN2 -> fc1(relu) -> fc2 -> +feat. RPB=16 rows/block, register-tiled.
// ============================================================================
__global__ void __launch_bounds__(256) mlp_kernel(
    const float* __restrict__ fc1w, const float* __restrict__ fc1b,
    const float* __restrict__ fc2w, const float* __restrict__ fc2b,
    const float* __restrict__ n2g, const float* __restrict__ n2b,
    float* __restrict__ out) {
    ull*   lnDup = reinterpret_cast<ull*>(dynsm);                  // [256][17]
    float* hS    = reinterpret_cast<float*>(dynsm + 256 * 17 * 8); // [16][520]
    const int t = threadIdx.x;
    const long row0 = (long)blockIdx.x * RPB;

    {
        const int w = t >> 5, l = t & 31;
        for (int rr = 0; rr < 2; ++rr) {
            const int r = w + 8 * rr;
            const float* frow = g_feat_buf + (row0 + r) * C_;
            float v[8], sum = 0.f;
#pragma unroll
            for (int k = 0; k < 8; ++k) { v[k] = frow[l + 32 * k]; sum += v[k]; }
#pragma unroll
            for (int o = 16; o; o >>= 1) sum += __shfl_xor_sync(FULL, sum, o);
            const float m = sum * (1.f / C_);
            float qv = 0.f;
#pragma unroll
            for (int k = 0; k < 8; ++k) { float d = v[k] - m; qv += d * d; }
#pragma unroll
            for (int o = 16; o; o >>= 1) qv += __shfl_xor_sync(FULL, qv, o);
            const float rs = rsqrtf(qv * (1.f / C_) + 1e-3f);
#pragma unroll
            for (int k = 0; k < 8; ++k) {
                const int i = l + 32 * k;
                const float x = (v[k] - m) * rs * n2g[i] + n2b[i];
                lnDup[i * 17 + r] = pk2(x, x);
            }
        }
    }
    __syncthreads();

    const int q  = t >> 6;
    const int cc = t & 63;

    {
        ull acc[4][4];
#pragma unroll
        for (int cp = 0; cp < 4; ++cp)
#pragma unroll
            for (int r = 0; r < 4; ++r) acc[cp][r] = 0ull;
        const float* wbase = fc1w + cc * 8;
#pragma unroll 1
        for (int i = 0; i < C_; ++i) {
            const ulonglong4 wv = *reinterpret_cast<const ulonglong4*>(wbase + (long)i * (2 * C_));
            const ull x0 = lnDup[i * 17 + 4 * q + 0];
            const ull x1 = lnDup[i * 17 + 4 * q + 1];
            const ull x2 = lnDup[i * 17 + 4 * q + 2];
            const ull x3 = lnDup[i * 17 + 4 * q + 3];
            fma2(acc[0][0], wv.x, x0); fma2(acc[0][1], wv.x, x1);
            fma2(acc[0][2], wv.x, x2); fma2(acc[0][3], wv.x, x3);
            fma2(acc[1][0], wv.y, x0); fma2(acc[1][1], wv.y, x1);
            fma2(acc[1][2], wv.y, x2); fma2(acc[1][3], wv.y, x3);
            fma2(acc[2][0], wv.z, x0); fma2(acc[2][1], wv.z, x1);
            fma2(acc[2][2], wv.z, x2); fma2(acc[2][3], wv.z, x3);
            fma2(acc[3][0], wv.w, x0); fma2(acc[3][1], wv.w, x1);
            fma2(acc[3][2], wv.w, x2); fma2(acc[3][3], wv.w, x3);
        }
        const float4 bA = *reinterpret_cast<const float4*>(fc1b + cc * 8);
        const float4 bB = *reinterpret_cast<const float4*>(fc1b + cc * 8 + 4);
        const float bias[8] = {bA.x, bA.y, bA.z, bA.w, bB.x, bB.y, bB.z, bB.w};
#pragma unroll
        for (int cp = 0; cp < 4; ++cp) {
            const int c0 = cc * 8 + 2 * cp;
#pragma unroll
            for (int r = 0; r < 4; ++r) {
                float a, b2; upk2(acc[cp][r], a, b2);
                hS[(4 * q + r) * 520 + c0]     = fmaxf(a + bias[2 * cp], 0.f);
                hS[(4 * q + r) * 520 + c0 + 1] = fmaxf(b2 + bias[2 * cp + 1], 0.f);
            }
        }
    }
    __syncthreads();

    {
        ull acc[2][4];
#pragma unroll
        for (int cp = 0; cp < 2; ++cp)
#pragma unroll
            for (int r = 0; r < 4; ++r) acc[cp][r] = 0ull;
        const float* wbase = fc2w + cc * 4;
#pragma unroll 2
        for (int j = 0; j < 2 * C_; ++j) {
            const ulonglong2 wv = *reinterpret_cast<const ulonglong2*>(wbase + (long)j * C_);
            const float h0 = hS[(4 * q + 0) * 520 + j];
            const float h1 = hS[(4 * q + 1) * 520 + j];
            const float h2 = hS[(4 * q + 2) * 520 + j];
            const float h3 = hS[(4 * q + 3) * 520 + j];
            const ull x0 = pk2(h0, h0), x1 = pk2(h1, h1), x2 = pk2(h2, h2), x3 = pk2(h3, h3);
            fma2(acc[0][0], wv.x, x0); fma2(acc[0][1], wv.x, x1);
            fma2(acc[0][2], wv.x, x2); fma2(acc[0][3], wv.x, x3);
            fma2(acc[1][0], wv.y, x0); fma2(acc[1][1], wv.y, x1);
            fma2(acc[1][2], wv.y, x2); fma2(acc[1][3], wv.y, x3);
        }
        const float4 bias = *reinterpret_cast<const float4*>(fc2b + cc * 4);
#pragma unroll
        for (int r = 0; r < 4; ++r) {
            const long row = row0 + 4 * q + r;
            const float4 res = *reinterpret_cast<const float4*>(g_feat_buf + row * C_ + cc * 4);
            float a0, a1, a2, a3;
            upk2(acc[0][r], a0, a1);
            upk2(acc[1][r], a2, a3);
            float4 o;
            o.x = a0 + bias.x + res.x;
            o.y = a1 + bias.y + res.y;
            o.z = a2 + bias.z + res.z;
            o.w = a3 + bias.w + res.w;
            *reinterpret_cast<float4*>(out + row * C_ + cc * 4) = o;
        }
    }
}

// ============================================================================
extern "C" void kernel_launch(void* const* d_in, const int* in_sizes, int n_in,
                              void* d_out, int out_size) {
    const float* xyz    = (const float*)d_in[0];
    const float* nxyz   = (const float*)d_in[1];
    const float* featin = (const float*)d_in[2];
    const float* wqkv   = (const float*)d_in[3];
    const float* projw  = (const float*)d_in[4];
    const float* projb  = (const float*)d_in[5];
    const float* densew = (const float*)d_in[6];
    const float* denseb = (const float*)d_in[7];
    const float* fc1w   = (const float*)d_in[8];
    const float* fc1b   = (const float*)d_in[9];
    const float* fc2w   = (const float*)d_in[10];
    const float* fc2b   = (const float*)d_in[11];
    const float* n1g    = (const float*)d_in[12];
    const float* n1b    = (const float*)d_in[13];
    const float* n2g    = (const float*)d_in[14];
    const float* n2b    = (const float*)d_in[15];
    float* out = (float*)d_out;

    (void)in_sizes; (void)n_in; (void)out_size;

    const int knn_smem  = N_ * (int)sizeof(float4);            // 64 KB
    const int attn_smem = (int)sizeof(SmemAll);                // ~90 KB
    const int mlp_smem  = 256 * 17 * 8 + 16 * 520 * 4;         // ~68 KB
    cudaFuncSetAttribute(knn_kernel, cudaFuncAttributeMaxDynamicSharedMemorySize, knn_smem);
    cudaFuncSetAttribute(attn_kernel, cudaFuncAttributeMaxDynamicSharedMemorySize, attn_smem);
    cudaFuncSetAttribute(mlp_kernel, cudaFuncAttributeMaxDynamicSharedMemorySize, mlp_smem);

    prep_kernel<<<36, 512>>>(wqkv);
    knn_kernel<<<dim3(NP_ / 8, B_), 256, knn_smem>>>(xyz, nxyz);
    attn_kernel<<<B_ * NP_ / G_, T_, attn_smem>>>(xyz, nxyz, featin, wqkv, projw, projb,
                                                  densew, denseb, n1g, n1b);
    mlp_kernel<<<B_ * NP_ / RPB, 256, mlp_smem>>>(fc1w, fc1b, fc2w, fc2b, n2g, n2b, out);
}

// round 10
// speedup vs baseline: 1.0825x; 1.0825x over previous
#include <cuda_runtime.h>
#include <cuda_bf16.h>
#include <cstdint>

typedef unsigned long long ull;
#define FULL 0xffffffffu

constexpr int B_  = 16;
constexpr int N_  = 4096;
constexpr int NP_ = 1024;
constexpr int K_  = 32;
constexpr int CIN = 128;
constexpr int CG  = 131;   // 3 + 128
constexpr int C_  = 256;
constexpr int H_  = 4;
constexpr int D_  = 64;
constexpr int TC  = 768;   // 3*C
constexpr int G_  = 4;     // groups per attn block (M = 128 rows)
constexpr int GP  = 34;    // per-group sub-pitch (floats) in xsT row
constexpr int XP  = 138;   // xsT row pitch (floats)
constexpr int T_  = 512;   // attn threads
constexpr int RPB = 16;    // rows per block in mlp kernel
constexpr int KC  = 48;    // K-chunk for mma (3 chunks: 144 >= 131, zero pad)
constexpr int AP  = 26;    // A/B smem row pitch in 32-bit words

// scratch (device globals: allocation-free rule)
__device__ int   g_idx_buf[B_ * NP_ * K_];
__device__ float g_feat_buf[B_ * NP_ * C_];
// Wq as bf16 hi/lo, [chunk][part][n=256][24 words of k-pairs]
__device__ __align__(16) unsigned g_wq[3 * 2 * 256 * 24];

extern __shared__ __align__(16) unsigned char dynsm[];

// ---------------- packed f32x2 helpers
__device__ __forceinline__ ull pk2(float a, float b) {
    ull r;
    asm("mov.b64 %0, {%1,%2};" : "=l"(r) : "f"(a), "f"(b));
    return r;
}
__device__ __forceinline__ void upk2(ull v, float& a, float& b) {
    asm("mov.b64 {%0,%1}, %2;" : "=f"(a), "=f"(b) : "l"(v));
}
__device__ __forceinline__ void fma2(ull& d, ull a, ull b) {
    asm("fma.rn.f32x2 %0, %1, %2, %3;" : "=l"(d) : "l"(a), "l"(b), "l"(d));
}

// ---------------- warp mma m16n8k16 bf16 (base PTX, works at compute_103)
__device__ __forceinline__ void mma16816(float* d, const unsigned* a, unsigned b0, unsigned b1) {
    asm volatile(
        "mma.sync.aligned.m16n8k16.row.col.f32.bf16.bf16.f32 "
        "{%0,%1,%2,%3}, {%4,%5,%6,%7}, {%8,%9}, {%0,%1,%2,%3};"
        : "+f"(d[0]), "+f"(d[1]), "+f"(d[2]), "+f"(d[3])
        : "r"(a[0]), "r"(a[1]), "r"(a[2]), "r"(a[3]), "r"(b0), "r"(b1));
}
__device__ __forceinline__ unsigned bf16pair(float x0, float x1) {
    const __nv_bfloat16 h0 = __float2bfloat16(x0), h1 = __float2bfloat16(x1);
    return (unsigned)__bfloat16_as_ushort(h0) | ((unsigned)__bfloat16_as_ushort(h1) << 16);
}

// ============================================================================
// K0: prep — Wq (131x256 fp32, k-major rows) -> bf16 hi/lo, [c][part][n][24w],
// k padded to 144 with zeros.
// ============================================================================
__global__ void __launch_bounds__(512) prep_kernel(const float* __restrict__ wqkv) {
    const int idx = blockIdx.x * 512 + threadIdx.x;
    if (idx >= 3 * 256 * 24) return;
    const int c = idx / 6144;
    const int rem = idx % 6144;
    const int n = rem / 24, j = rem % 24;
    const int k = c * KC + 2 * j;
    const float x0 = (k < CG) ? wqkv[(long)k * TC + n] : 0.f;
    const float x1 = (k + 1 < CG) ? wqkv[(long)(k + 1) * TC + n] : 0.f;
    const __nv_bfloat16 h0 = __float2bfloat16(x0), h1 = __float2bfloat16(x1);
    const float r0 = x0 - __bfloat162float(h0), r1 = x1 - __bfloat162float(h1);
    g_wq[(c * 2 + 0) * 6144 + n * 24 + j] = bf16pair(x0, x1);   // hi
    g_wq[(c * 2 + 1) * 6144 + n * 24 + j] = bf16pair(r0, r1);   // lo
}

// ============================================================================
// K1: KNN. One warp per query, max-replacement top-32 (set-only).
// ============================================================================
__global__ void __launch_bounds__(256) knn_kernel(const float* __restrict__ xyz,
                                                  const float* __restrict__ nxyz) {
    float4* pts = reinterpret_cast<float4*>(dynsm);
    const int b = blockIdx.y;
    const float* xb = xyz + (long)b * N_ * 3;
    for (int j = threadIdx.x; j < N_; j += 256) {
        float x = xb[j * 3 + 0], y = xb[j * 3 + 1], z = xb[j * 3 + 2];
        pts[j] = make_float4(x, y, z, x * x + y * y + z * z);
    }
    __syncthreads();

    const int warp = threadIdx.x >> 5, lane = threadIdx.x & 31;
    const int p = blockIdx.x * 8 + warp;
    const float* q = nxyz + ((long)b * NP_ + p) * 3;
    const float qx = q[0], qy = q[1], qz = q[2];

    float4 c0 = pts[lane];
    float bestd = c0.w - 2.f * (qx * c0.x + qy * c0.y + qz * c0.z);
    int besti = lane;

    float curmax = bestd;
#pragma unroll
    for (int o = 16; o; o >>= 1) curmax = fmaxf(curmax, __shfl_xor_sync(FULL, curmax, o));

    for (int j0 = K_; j0 < N_; j0 += K_) {
        float4 c = pts[j0 + lane];
        float d = c.w - 2.f * (qx * c.x + qy * c.y + qz * c.z);
        unsigned mset = __ballot_sync(FULL, d < curmax);
        while (mset) {
            int src = __ffs(mset) - 1;
            mset &= mset - 1;
            float cd = __shfl_sync(FULL, d, src);
            if (cd < curmax) {
                unsigned vict = __ballot_sync(FULL, bestd == curmax);
                int vl = __ffs(vict) - 1;
                if (lane == vl) { bestd = cd; besti = j0 + src; }
                float v = bestd;
#pragma unroll
                for (int o = 16; o; o >>= 1) v = fmaxf(v, __shfl_xor_sync(FULL, v, o));
                curmax = v;
            }
        }
    }
    g_idx_buf[((long)b * NP_ + p) * K_ + lane] = besti;
}

// ============================================================================
// K2: fused group -> LN -> Q GEMM (mma.sync bf16 split) -> collapsed K/V
// attention -> proj+dense. M=128 (4 groups x 32 rows), N=256, K=131(->144).
// (Round-8 configuration: the fastest attn measured so far.)
// ============================================================================
struct __align__(16) SmemAll {
    unsigned Abf[2][128][AP];   // x bf16 hi/lo, one 48-K chunk, [m][k-pair words]
    unsigned Bbf[2][256][AP];   // Wq bf16 hi/lo, one chunk, [n][k-pair words]
    float xsT[CG][XP];          // LN'd grouped features, transposed
    float pad0[2];
    float qm[G_][C_];
    float gmax[G_][132];
    float z[G_][H_][132];
    float y[G_][H_][132];
    float attnw[G_][H_][K_];
    float sat[G_][C_];
    int   nidx[G_][K_];
    float q3[G_][4];
};

__global__ void __launch_bounds__(T_, 1) attn_kernel(
    const float* __restrict__ xyz, const float* __restrict__ nxyz,
    const float* __restrict__ featin, const float* __restrict__ wqkv,
    const float* __restrict__ projw, const float* __restrict__ projb,
    const float* __restrict__ densew, const float* __restrict__ denseb,
    const float* __restrict__ n1g, const float* __restrict__ n1b) {
    SmemAll& s = *reinterpret_cast<SmemAll*>(dynsm);
    const int t = threadIdx.x;
    const int w = t >> 5, lane = t & 31;
    const int grp0 = blockIdx.x * G_;
    const int b = grp0 >> 10, p0 = grp0 & 1023;

    if (t < G_ * K_) {
        int g = t >> 5, r = t & 31;
        s.nidx[g][r] = g_idx_buf[(long)(grp0 + g) * K_ + r];
    }
    if (t < G_ * 3) {
        int g = t / 3, c = t % 3;
        s.q3[g][c] = nxyz[((long)b * NP_ + p0 + g) * 3 + c];
    }
    __syncthreads();

    // gather: relative xyz (rows 0..2) + features (rows 3..130)
    if (t < G_ * K_) {
        int g = t >> 5, r = t & 31;
        int j = s.nidx[g][r];
        const float* xp = xyz + ((long)b * N_ + j) * 3;
        s.xsT[0][g * GP + r] = xp[0] - s.q3[g][0];
        s.xsT[1][g * GP + r] = xp[1] - s.q3[g][1];
        s.xsT[2][g * GP + r] = xp[2] - s.q3[g][2];
    }
    for (int e = t; e < G_ * K_ * CIN; e += T_) {
        int g = e >> 12, r = (e >> 7) & 31, i = e & 127;
        s.xsT[3 + i][g * GP + r] = featin[((long)b * N_ + s.nidx[g][r]) * CIN + i];
    }
    __syncthreads();

    // max over K of raw gf (dense branch) before LN overwrites
    for (int e = t; e < G_ * CG; e += T_) {
        int g = e / CG, i = e - g * CG;
        float m = s.xsT[i][g * GP];
#pragma unroll
        for (int r = 1; r < K_; ++r) m = fmaxf(m, s.xsT[i][g * GP + r]);
        s.gmax[g][i] = m;
    }
    __syncthreads();

    // LayerNorm over CG=131 per row; warp w (0..15) owns rows w+16k
    for (int k = 0; k < 8; ++k) {
        const int row = w + 16 * k;
        const int g = row >> 5, r = row & 31;
        float v[5];
        int kn = 0;
        float sum = 0.f;
        for (int ii = lane; ii < CG; ii += 32) { v[kn] = s.xsT[ii][g * GP + r]; sum += v[kn]; ++kn; }
#pragma unroll
        for (int o = 16; o; o >>= 1) sum += __shfl_xor_sync(FULL, sum, o);
        const float m = sum * (1.f / CG);
        float qv = 0.f;
        for (int kk = 0; kk < kn; ++kk) { float d = v[kk] - m; qv += d * d; }
#pragma unroll
        for (int o = 16; o; o >>= 1) qv += __shfl_xor_sync(FULL, qv, o);
        const float rs = rsqrtf(qv * (1.f / CG) + 1e-3f);
        kn = 0;
        for (int ii = lane; ii < CG; ii += 32) {
            s.xsT[ii][g * GP + r] = (v[kn] - m) * rs * n1g[ii] + n1b[ii];
            ++kn;
        }
    }
    __syncthreads();

    // ================= Q GEMM on tensor cores (mma.sync, split bf16) ========
    const int gq = w & 3;
    const int mbase = 32 * gq;
    const int nbase = (w >> 2) * 64;
    const int lp = lane >> 2, lq = lane & 3;
    float cfr[2][8][4];
#pragma unroll
    for (int mt = 0; mt < 2; ++mt)
#pragma unroll
        for (int j = 0; j < 8; ++j)
#pragma unroll
            for (int e = 0; e < 4; ++e) cfr[mt][j][e] = 0.f;

    const unsigned* A0 = &s.Abf[0][0][0];
    const unsigned* A1 = &s.Abf[1][0][0];
    const unsigned* B0 = &s.Bbf[0][0][0];
    const unsigned* B1 = &s.Bbf[1][0][0];

    for (int c = 0; c < 3; ++c) {
        // --- convert A chunk c: xsT fp32 -> bf16 hi/lo pairs
        {
            const int mq = t & 127;
            const int qd = t >> 7;
            const int colx = (mq >> 5) * GP + (mq & 31);
#pragma unroll
            for (int jj = 0; jj < 6; ++jj) {
                const int j = qd * 6 + jj;
                const int k = c * KC + 2 * j;
                const float x0 = (k < CG) ? s.xsT[k][colx] : 0.f;
                const float x1 = (k + 1 < CG) ? s.xsT[k + 1][colx] : 0.f;
                const __nv_bfloat16 h0 = __float2bfloat16(x0), h1 = __float2bfloat16(x1);
                s.Abf[0][mq][j] = (unsigned)__bfloat16_as_ushort(h0) |
                                  ((unsigned)__bfloat16_as_ushort(h1) << 16);
                s.Abf[1][mq][j] = bf16pair(x0 - __bfloat162float(h0), x1 - __bfloat162float(h1));
            }
        }
        // --- copy B chunk c (hi+lo), re-pitch 24 -> 26 words
        {
            const uint2* src = reinterpret_cast<const uint2*>(g_wq) + (long)c * 6144;
            uint2* dst = reinterpret_cast<uint2*>(&s.Bbf[0][0][0]);
            for (int i = t; i < 6144; i += T_) {
                const int row = i / 12, j2 = i % 12;
                dst[row * 13 + j2] = src[i];
            }
        }
        __syncthreads();

        // --- 3 k-steps of m16n8k16, products hh + hl + lh
#pragma unroll
        for (int ks = 0; ks < 3; ++ks) {
            const int ko = ks * 8 + lq;
            unsigned ah[2][4], al[2][4];
#pragma unroll
            for (int mt = 0; mt < 2; ++mt) {
                const int r0 = (mbase + mt * 16 + lp) * AP;
                const int r8 = r0 + 8 * AP;
                ah[mt][0] = A0[r0 + ko];     ah[mt][1] = A0[r8 + ko];
                ah[mt][2] = A0[r0 + ko + 4]; ah[mt][3] = A0[r8 + ko + 4];
                al[mt][0] = A1[r0 + ko];     al[mt][1] = A1[r8 + ko];
                al[mt][2] = A1[r0 + ko + 4]; al[mt][3] = A1[r8 + ko + 4];
            }
#pragma unroll
            for (int j = 0; j < 8; ++j) {
                const int nr = (nbase + j * 8 + lp) * AP;
                const unsigned bh0 = B0[nr + ko], bh1 = B0[nr + ko + 4];
                const unsigned bl0 = B1[nr + ko], bl1 = B1[nr + ko + 4];
#pragma unroll
                for (int mt = 0; mt < 2; ++mt) {
                    mma16816(cfr[mt][j], ah[mt], bh0, bh1);
                    mma16816(cfr[mt][j], ah[mt], bl0, bl1);
                    mma16816(cfr[mt][j], al[mt], bh0, bh1);
                }
            }
        }
        __syncthreads();
    }

    // per-group column max from C fragments
#pragma unroll
    for (int j = 0; j < 8; ++j) {
        float ve = fmaxf(fmaxf(cfr[0][j][0], cfr[0][j][2]), fmaxf(cfr[1][j][0], cfr[1][j][2]));
        float vo = fmaxf(fmaxf(cfr[0][j][1], cfr[0][j][3]), fmaxf(cfr[1][j][1], cfr[1][j][3]));
#pragma unroll
        for (int o = 4; o <= 16; o <<= 1) {
            ve = fmaxf(ve, __shfl_xor_sync(FULL, ve, o));
            vo = fmaxf(vo, __shfl_xor_sync(FULL, vo, o));
        }
        if (lane < 4) {
            s.qm[gq][nbase + j * 8 + 2 * lane]     = ve;
            s.qm[gq][nbase + j * 8 + 2 * lane + 1] = vo;
        }
    }
    __syncthreads();

    // ---- z[g][h][i] = sum_d qm[g][h*64+d] * Wk[i][h*64+d]; warp-per-i
    {
        float4 qa[G_], qb[G_];
#pragma unroll
        for (int g = 0; g < G_; ++g) {
            qa[g] = reinterpret_cast<const float4*>(s.qm[g])[lane];
            qb[g] = reinterpret_cast<const float4*>(s.qm[g])[32 + lane];
        }
        for (int i = w; i < CG; i += 16) {
            const float4* wr = reinterpret_cast<const float4*>(wqkv + (long)i * TC + C_);
            const float4 w0 = wr[lane];
            const float4 w1 = wr[32 + lane];
            float s0[G_], s1[G_];
#pragma unroll
            for (int g = 0; g < G_; ++g) {
                s0[g] = w0.x * qa[g].x + w0.y * qa[g].y + w0.z * qa[g].z + w0.w * qa[g].w;
                s1[g] = w1.x * qb[g].x + w1.y * qb[g].y + w1.z * qb[g].z + w1.w * qb[g].w;
            }
#pragma unroll
            for (int o = 8; o; o >>= 1) {
#pragma unroll
                for (int g = 0; g < G_; ++g) {
                    s0[g] += __shfl_xor_sync(FULL, s0[g], o);
                    s1[g] += __shfl_xor_sync(FULL, s1[g], o);
                }
            }
            if ((lane & 15) == 0) {
                const int h0 = lane >> 4;
#pragma unroll
                for (int g = 0; g < G_; ++g) {
                    s.z[g][h0][i]     = s0[g];
                    s.z[g][h0 + 2][i] = s1[g];
                }
            }
        }
    }
    __syncthreads();

    // ---- logits + softmax: warp w = (g,h), lane = row r
    {
        const int g = w >> 2, h = w & 3, r = lane;
        float a = 0.f;
#pragma unroll 4
        for (int i = 0; i < CG; ++i) a += s.xsT[i][g * GP + r] * s.z[g][h][i];
        a *= 0.0625f;
        float mx = a;
#pragma unroll
        for (int o = 16; o; o >>= 1) mx = fmaxf(mx, __shfl_xor_sync(FULL, mx, o));
        const float e = expf(a - mx);
        float ss = e;
#pragma unroll
        for (int o = 16; o; o >>= 1) ss += __shfl_xor_sync(FULL, ss, o);
        s.attnw[g][h][r] = e / ss;
    }
    __syncthreads();

    // ---- y[g][h][i] = sum_r attnw[g][h][r] * x[i][r]
    for (int e = t; e < G_ * H_ * CG; e += T_) {
        const int i = e % CG;
        const int gh = e / CG;
        const int g = gh >> 2, h = gh & 3;
        const ull* aw = reinterpret_cast<const ull*>(s.attnw[g][h]);
        const ull* xr = reinterpret_cast<const ull*>(&s.xsT[i][g * GP]);
        ull acc = 0ull;
#pragma unroll
        for (int rp = 0; rp < 16; ++rp) fma2(acc, xr[rp], aw[rp]);
        float a, b2; upk2(acc, a, b2);
        s.y[g][h][i] = a + b2;
    }
    __syncthreads();

    // ---- sat[g][c] = sum_i y[g][h][i] * Wv[i][c]; thread = (c, group-pair)
    {
        const int c = t & 255, g2 = t >> 8;
        const int h = c >> 6;
        const float* wv = wqkv + 2 * C_ + c;
        float a0 = 0.f, a1 = 0.f;
#pragma unroll 8
        for (int i = 0; i < CG; ++i) {
            const float wvi = wv[(long)i * TC];
            a0 += s.y[g2][h][i] * wvi;
            a1 += s.y[g2 + 2][h][i] * wvi;
        }
        s.sat[g2][c] = a0;
        s.sat[g2 + 2][c] = a1;
    }
    __syncthreads();

    // ---- proj (relu) + dense (relu): thread = (c, group-pair)
    {
        const int c = t & 255, g2 = t >> 8;
        float p0 = 0.f, p1 = 0.f;
        const float* wp = projw + c;
#pragma unroll 8
        for (int i = 0; i < C_; ++i) {
            const float wv = wp[(long)i * C_];
            p0 += s.sat[g2][i] * wv;
            p1 += s.sat[g2 + 2][i] * wv;
        }
        float d0 = 0.f, d1 = 0.f;
        const float* wd = densew + c;
#pragma unroll 8
        for (int i = 0; i < CG; ++i) {
            const float wv = wd[(long)i * C_];
            d0 += s.gmax[g2][i] * wv;
            d1 += s.gmax[g2 + 2][i] * wv;
        }
        const float pb = projb[c], db = denseb[c];
        g_feat_buf[(long)(grp0 + g2) * C_ + c]     = fmaxf(p0 + pb, 0.f) + fmaxf(d0 + db, 0.f);
        g_feat_buf[(long)(grp0 + g2 + 2) * C_ + c] = fmaxf(p1 + pb, 0.f) + fmaxf(d1 + db, 0.f);
    }
}

// ============================================================================
// K3: LN2 -> fc1(relu) -> fc2 -> +feat. RPB=16 rows/block, register-tiled.
// This round: lnT stored as plain fp32 (smem 68 -> 52 KB -> 4 blocks/SM) and
// fc1 weight stream unrolled x2 (2 LDG.128-pairs in flight).
// ============================================================================
__global__ void __launch_bounds__(256, 4) mlp_kernel(
    const float* __restrict__ fc1w, const float* __restrict__ fc1b,
    const float* __restrict__ fc2w, const float* __restrict__ fc2b,
    const float* __restrict__ n2g, const float* __restrict__ n2b,
    float* __restrict__ out) {
    float* lnT = reinterpret_cast<float*>(dynsm);                   // [256][18]
    float* hS  = reinterpret_cast<float*>(dynsm + 256 * 18 * 4);    // [16][520]
    const int t = threadIdx.x;
    const long row0 = (long)blockIdx.x * RPB;

    // LN per row: warp w handles rows w and w+8
    {
        const int w = t >> 5, l = t & 31;
        for (int rr = 0; rr < 2; ++rr) {
            const int r = w + 8 * rr;
            const float* frow = g_feat_buf + (row0 + r) * C_;
            float v[8], sum = 0.f;
#pragma unroll
            for (int k = 0; k < 8; ++k) { v[k] = frow[l + 32 * k]; sum += v[k]; }
#pragma unroll
            for (int o = 16; o; o >>= 1) sum += __shfl_xor_sync(FULL, sum, o);
            const float m = sum * (1.f / C_);
            float qv = 0.f;
#pragma unroll
            for (int k = 0; k < 8; ++k) { float d = v[k] - m; qv += d * d; }
#pragma unroll
            for (int o = 16; o; o >>= 1) qv += __shfl_xor_sync(FULL, qv, o);
            const float rs = rsqrtf(qv * (1.f / C_) + 1e-3f);
#pragma unroll
            for (int k = 0; k < 8; ++k) {
                const int i = l + 32 * k;
                lnT[i * 18 + r] = (v[k] - m) * rs * n2g[i] + n2b[i];
            }
        }
    }
    __syncthreads();

    const int q  = t >> 6;   // row group: rows 4q..4q+3
    const int cc = t & 63;

    // fc1: cols cc*8 .. cc*8+7 (4 col-pairs) x 4 rows
    {
        ull acc[4][4];
#pragma unroll
        for (int cp = 0; cp < 4; ++cp)
#pragma unroll
            for (int r = 0; r < 4; ++r) acc[cp][r] = 0ull;
        const float* wbase = fc1w + cc * 8;
#pragma unroll 2
        for (int i = 0; i < C_; ++i) {
            const ulonglong4 wv = *reinterpret_cast<const ulonglong4*>(wbase + (long)i * (2 * C_));
            const float xv0 = lnT[i * 18 + 4 * q + 0];
            const float xv1 = lnT[i * 18 + 4 * q + 1];
            const float xv2 = lnT[i * 18 + 4 * q + 2];
            const float xv3 = lnT[i * 18 + 4 * q + 3];
            const ull x0 = pk2(xv0, xv0), x1 = pk2(xv1, xv1);
            const ull x2 = pk2(xv2, xv2), x3 = pk2(xv3, xv3);
            fma2(acc[0][0], wv.x, x0); fma2(acc[0][1], wv.x, x1);
            fma2(acc[0][2], wv.x, x2); fma2(acc[0][3], wv.x, x3);
            fma2(acc[1][0], wv.y, x0); fma2(acc[1][1], wv.y, x1);
            fma2(acc[1][2], wv.y, x2); fma2(acc[1][3], wv.y, x3);
            fma2(acc[2][0], wv.z, x0); fma2(acc[2][1], wv.z, x1);
            fma2(acc[2][2], wv.z, x2); fma2(acc[2][3], wv.z, x3);
            fma2(acc[3][0], wv.w, x0); fma2(acc[3][1], wv.w, x1);
            fma2(acc[3][2], wv.w, x2); fma2(acc[3][3], wv.w, x3);
        }
        const float4 bA = *reinterpret_cast<const float4*>(fc1b + cc * 8);
        const float4 bB = *reinterpret_cast<const float4*>(fc1b + cc * 8 + 4);
        const float bias[8] = {bA.x, bA.y, bA.z, bA.w, bB.x, bB.y, bB.z, bB.w};
#pragma unroll
        for (int cp = 0; cp < 4; ++cp) {
            const int c0 = cc * 8 + 2 * cp;
#pragma unroll
            for (int r = 0; r < 4; ++r) {
                float a, b2; upk2(acc[cp][r], a, b2);
                hS[(4 * q + r) * 520 + c0]     = fmaxf(a + bias[2 * cp], 0.f);
                hS[(4 * q + r) * 520 + c0 + 1] = fmaxf(b2 + bias[2 * cp + 1], 0.f);
            }
        }
    }
    __syncthreads();

    // fc2: cols cc*4 .. cc*4+3 (2 col-pairs) x 4 rows, K=512
    {
        ull acc[2][4];
#pragma unroll
        for (int cp = 0; cp < 2; ++cp)
#pragma unroll
            for (int r = 0; r < 4; ++r) acc[cp][r] = 0ull;
        const float* wbase = fc2w + cc * 4;
#pragma unroll 2
        for (int j = 0; j < 2 * C_; ++j) {
            const ulonglong2 wv = *reinterpret_cast<const ulonglong2*>(wbase + (long)j * C_);
            const float h0 = hS[(4 * q + 0) * 520 + j];
            const float h1 = hS[(4 * q + 1) * 520 + j];
            const float h2 = hS[(4 * q + 2) * 520 + j];
            const float h3 = hS[(4 * q + 3) * 520 + j];
            const ull x0 = pk2(h0, h0), x1 = pk2(h1, h1), x2 = pk2(h2, h2), x3 = pk2(h3, h3);
            fma2(acc[0][0], wv.x, x0); fma2(acc[0][1], wv.x, x1);
            fma2(acc[0][2], wv.x, x2); fma2(acc[0][3], wv.x, x3);
            fma2(acc[1][0], wv.y, x0); fma2(acc[1][1], wv.y, x1);
            fma2(acc[1][2], wv.y, x2); fma2(acc[1][3], wv.y, x3);
        }
        const float4 bias = *reinterpret_cast<const float4*>(fc2b + cc * 4);
#pragma unroll
        for (int r = 0; r < 4; ++r) {
            const long row = row0 + 4 * q + r;
            const float4 res = *reinterpret_cast<const float4*>(g_feat_buf + row * C_ + cc * 4);
            float a0, a1, a2, a3;
            upk2(acc[0][r], a0, a1);
            upk2(acc[1][r], a2, a3);
            float4 o;
            o.x = a0 + bias.x + res.x;
            o.y = a1 + bias.y + res.y;
            o.z = a2 + bias.z + res.z;
            o.w = a3 + bias.w + res.w;
            *reinterpret_cast<float4*>(out + row * C_ + cc * 4) = o;
        }
    }
}

// ============================================================================
extern "C" void kernel_launch(void* const* d_in, const int* in_sizes, int n_in,
                              void* d_out, int out_size) {
    const float* xyz    = (const float*)d_in[0];
    const float* nxyz   = (const float*)d_in[1];
    const float* featin = (const float*)d_in[2];
    const float* wqkv   = (const float*)d_in[3];
    const float* projw  = (const float*)d_in[4];
    const float* projb  = (const float*)d_in[5];
    const float* densew = (const float*)d_in[6];
    const float* denseb = (const float*)d_in[7];
    const float* fc1w   = (const float*)d_in[8];
    const float* fc1b   = (const float*)d_in[9];
    const float* fc2w   = (const float*)d_in[10];
    const float* fc2b   = (const float*)d_in[11];
    const float* n1g    = (const float*)d_in[12];
    const float* n1b    = (const float*)d_in[13];
    const float* n2g    = (const float*)d_in[14];
    const float* n2b    = (const float*)d_in[15];
    float* out = (float*)d_out;

    (void)in_sizes; (void)n_in; (void)out_size;

    const int knn_smem  = N_ * (int)sizeof(float4);            // 64 KB
    const int attn_smem = (int)sizeof(SmemAll);                // ~178 KB
    const int mlp_smem  = 256 * 18 * 4 + 16 * 520 * 4;         // ~51.7 KB
    cudaFuncSetAttribute(knn_kernel, cudaFuncAttributeMaxDynamicSharedMemorySize, knn_smem);
    cudaFuncSetAttribute(attn_kernel, cudaFuncAttributeMaxDynamicSharedMemorySize, attn_smem);
    cudaFuncSetAttribute(mlp_kernel, cudaFuncAttributeMaxDynamicSharedMemorySize, mlp_smem);

    prep_kernel<<<36, 512>>>(wqkv);
    knn_kernel<<<dim3(NP_ / 8, B_), 256, knn_smem>>>(xyz, nxyz);
    attn_kernel<<<B_ * NP_ / G_, T_, attn_smem>>>(xyz, nxyz, featin, wqkv, projw, projb,
                                                  densew, denseb, n1g, n1b);
    mlp_kernel<<<B_ * NP_ / RPB, 256, mlp_smem>>>(fc1w, fc1b, fc2w, fc2b, n2g, n2b, out);
}

// round 11
// speedup vs baseline: 1.0865x; 1.0036x over previous
#include <cuda_runtime.h>
#include <cuda_bf16.h>
#include <cstdint>

typedef unsigned long long ull;
#define FULL 0xffffffffu

constexpr int B_  = 16;
constexpr int N_  = 4096;
constexpr int NP_ = 1024;
constexpr int K_  = 32;
constexpr int CIN = 128;
constexpr int CG  = 131;   // 3 + 128
constexpr int C_  = 256;
constexpr int H_  = 4;
constexpr int D_  = 64;
constexpr int TC  = 768;   // 3*C
constexpr int G_  = 4;     // groups per attn block (M = 128 rows)
constexpr int GP  = 34;    // per-group sub-pitch (floats) in xsT row
constexpr int XP  = 138;   // xsT row pitch (floats)
constexpr int T_  = 512;   // attn threads
constexpr int KC  = 48;    // K-chunk for mma (AP=26 conflict-free pattern)
constexpr int AP  = 26;    // A/B smem row pitch in 32-bit words
constexpr int MR  = 16;    // mlp rows per block
constexpr int P1  = 154;   // lnPk pitch words (154 mod 32 == 26)
constexpr int P2  = 282;   // hPk pitch words  (282 mod 32 == 26)

// scratch (device globals: allocation-free rule)
__device__ int   g_idx_buf[B_ * NP_ * K_];
__device__ float g_feat_buf[B_ * NP_ * C_];
// weights as bf16 hi/lo, [chunk][part][n][24 words of k-pairs]
__device__ __align__(16) unsigned g_wq[3 * 2 * 256 * 24];
__device__ __align__(16) unsigned g_w1[6 * 2 * 512 * 24];
__device__ __align__(16) unsigned g_w2[11 * 2 * 256 * 24];

extern __shared__ __align__(16) unsigned char dynsm[];

// ---------------- packed f32x2 helpers
__device__ __forceinline__ ull pk2(float a, float b) {
    ull r;
    asm("mov.b64 %0, {%1,%2};" : "=l"(r) : "f"(a), "f"(b));
    return r;
}
__device__ __forceinline__ void upk2(ull v, float& a, float& b) {
    asm("mov.b64 {%0,%1}, %2;" : "=f"(a), "=f"(b) : "l"(v));
}
__device__ __forceinline__ void fma2(ull& d, ull a, ull b) {
    asm("fma.rn.f32x2 %0, %1, %2, %3;" : "=l"(d) : "l"(a), "l"(b), "l"(d));
}

// ---------------- warp mma m16n8k16 bf16 (base PTX, works at compute_103)
__device__ __forceinline__ void mma16816(float* d, const unsigned* a, unsigned b0, unsigned b1) {
    asm volatile(
        "mma.sync.aligned.m16n8k16.row.col.f32.bf16.bf16.f32 "
        "{%0,%1,%2,%3}, {%4,%5,%6,%7}, {%8,%9}, {%0,%1,%2,%3};"
        : "+f"(d[0]), "+f"(d[1]), "+f"(d[2]), "+f"(d[3])
        : "r"(a[0]), "r"(a[1]), "r"(a[2]), "r"(a[3]), "r"(b0), "r"(b1));
}
__device__ __forceinline__ unsigned bf16pair(float x0, float x1) {
    const __nv_bfloat16 h0 = __float2bfloat16(x0), h1 = __float2bfloat16(x1);
    return (unsigned)__bfloat16_as_ushort(h0) | ((unsigned)__bfloat16_as_ushort(h1) << 16);
}

// ============================================================================
// K0: prep — convert Wq, fc1w, fc2w to bf16 hi/lo [c][part][n][24] layouts.
// ============================================================================
__global__ void __launch_bounds__(512) prep_kernel(const float* __restrict__ wqkv,
                                                   const float* __restrict__ fc1w,
                                                   const float* __restrict__ fc2w) {
    const int idx = blockIdx.x * 512 + threadIdx.x;
    if (idx < 18432) {                       // Wq: 3 chunks x 256 n x 24 j
        const int c = idx / 6144, rem = idx % 6144;
        const int n = rem / 24, j = rem % 24;
        const int k = c * KC + 2 * j;
        const float x0 = (k < CG) ? wqkv[(long)k * TC + n] : 0.f;
        const float x1 = (k + 1 < CG) ? wqkv[(long)(k + 1) * TC + n] : 0.f;
        const __nv_bfloat16 h0 = __float2bfloat16(x0), h1 = __float2bfloat16(x1);
        g_wq[(c * 2 + 0) * 6144 + n * 24 + j] = bf16pair(x0, x1);
        g_wq[(c * 2 + 1) * 6144 + n * 24 + j] =
            bf16pair(x0 - __bfloat162float(h0), x1 - __bfloat162float(h1));
    } else if (idx < 92160) {                // fc1w: 6 chunks x 512 n x 24 j
        const int i = idx - 18432;
        const int c = i / 12288, rem = i % 12288;
        const int n = rem / 24, j = rem % 24;
        const int k = c * KC + 2 * j;
        const float x0 = (k < C_) ? fc1w[(long)k * (2 * C_) + n] : 0.f;
        const float x1 = (k + 1 < C_) ? fc1w[(long)(k + 1) * (2 * C_) + n] : 0.f;
        const __nv_bfloat16 h0 = __float2bfloat16(x0), h1 = __float2bfloat16(x1);
        g_w1[(c * 2 + 0) * 12288 + n * 24 + j] = bf16pair(x0, x1);
        g_w1[(c * 2 + 1) * 12288 + n * 24 + j] =
            bf16pair(x0 - __bfloat162float(h0), x1 - __bfloat162float(h1));
    } else if (idx < 159744) {               // fc2w: 11 chunks x 256 n x 24 j
        const int i = idx - 92160;
        const int c = i / 6144, rem = i % 6144;
        const int n = rem / 24, j = rem % 24;
        const int k = c * KC + 2 * j;
        const float x0 = (k < 2 * C_) ? fc2w[(long)k * C_ + n] : 0.f;
        const float x1 = (k + 1 < 2 * C_) ? fc2w[(long)(k + 1) * C_ + n] : 0.f;
        const __nv_bfloat16 h0 = __float2bfloat16(x0), h1 = __float2bfloat16(x1);
        g_w2[(c * 2 + 0) * 6144 + n * 24 + j] = bf16pair(x0, x1);
        g_w2[(c * 2 + 1) * 6144 + n * 24 + j] =
            bf16pair(x0 - __bfloat162float(h0), x1 - __bfloat162float(h1));
    }
}

// ============================================================================
// K1: KNN. One warp per query, max-replacement top-32 (set-only).
// ============================================================================
__global__ void __launch_bounds__(256) knn_kernel(const float* __restrict__ xyz,
                                                  const float* __restrict__ nxyz) {
    float4* pts = reinterpret_cast<float4*>(dynsm);
    const int b = blockIdx.y;
    const float* xb = xyz + (long)b * N_ * 3;
    for (int j = threadIdx.x; j < N_; j += 256) {
        float x = xb[j * 3 + 0], y = xb[j * 3 + 1], z = xb[j * 3 + 2];
        pts[j] = make_float4(x, y, z, x * x + y * y + z * z);
    }
    __syncthreads();

    const int warp = threadIdx.x >> 5, lane = threadIdx.x & 31;
    const int p = blockIdx.x * 8 + warp;
    const float* q = nxyz + ((long)b * NP_ + p) * 3;
    const float qx = q[0], qy = q[1], qz = q[2];

    float4 c0 = pts[lane];
    float bestd = c0.w - 2.f * (qx * c0.x + qy * c0.y + qz * c0.z);
    int besti = lane;

    float curmax = bestd;
#pragma unroll
    for (int o = 16; o; o >>= 1) curmax = fmaxf(curmax, __shfl_xor_sync(FULL, curmax, o));

    for (int j0 = K_; j0 < N_; j0 += K_) {
        float4 c = pts[j0 + lane];
        float d = c.w - 2.f * (qx * c.x + qy * c.y + qz * c.z);
        unsigned mset = __ballot_sync(FULL, d < curmax);
        while (mset) {
            int src = __ffs(mset) - 1;
            mset &= mset - 1;
            float cd = __shfl_sync(FULL, d, src);
            if (cd < curmax) {
                unsigned vict = __ballot_sync(FULL, bestd == curmax);
                int vl = __ffs(vict) - 1;
                if (lane == vl) { bestd = cd; besti = j0 + src; }
                float v = bestd;
#pragma unroll
                for (int o = 16; o; o >>= 1) v = fmaxf(v, __shfl_xor_sync(FULL, v, o));
                curmax = v;
            }
        }
    }
    g_idx_buf[((long)b * NP_ + p) * K_ + lane] = besti;
}

// ============================================================================
// K2: attn (round-10 configuration, unchanged — best measured).
// ============================================================================
struct __align__(16) SmemAll {
    unsigned Abf[2][128][AP];
    unsigned Bbf[2][256][AP];
    float xsT[CG][XP];
    float pad0[2];
    float qm[G_][C_];
    float gmax[G_][132];
    float z[G_][H_][132];
    float y[G_][H_][132];
    float attnw[G_][H_][K_];
    float sat[G_][C_];
    int   nidx[G_][K_];
    float q3[G_][4];
};

__global__ void __launch_bounds__(T_, 1) attn_kernel(
    const float* __restrict__ xyz, const float* __restrict__ nxyz,
    const float* __restrict__ featin, const float* __restrict__ wqkv,
    const float* __restrict__ projw, const float* __restrict__ projb,
    const float* __restrict__ densew, const float* __restrict__ denseb,
    const float* __restrict__ n1g, const float* __restrict__ n1b) {
    SmemAll& s = *reinterpret_cast<SmemAll*>(dynsm);
    const int t = threadIdx.x;
    const int w = t >> 5, lane = t & 31;
    const int grp0 = blockIdx.x * G_;
    const int b = grp0 >> 10, p0 = grp0 & 1023;

    if (t < G_ * K_) {
        int g = t >> 5, r = t & 31;
        s.nidx[g][r] = g_idx_buf[(long)(grp0 + g) * K_ + r];
    }
    if (t < G_ * 3) {
        int g = t / 3, c = t % 3;
        s.q3[g][c] = nxyz[((long)b * NP_ + p0 + g) * 3 + c];
    }
    __syncthreads();

    if (t < G_ * K_) {
        int g = t >> 5, r = t & 31;
        int j = s.nidx[g][r];
        const float* xp = xyz + ((long)b * N_ + j) * 3;
        s.xsT[0][g * GP + r] = xp[0] - s.q3[g][0];
        s.xsT[1][g * GP + r] = xp[1] - s.q3[g][1];
        s.xsT[2][g * GP + r] = xp[2] - s.q3[g][2];
    }
    for (int e = t; e < G_ * K_ * CIN; e += T_) {
        int g = e >> 12, r = (e >> 7) & 31, i = e & 127;
        s.xsT[3 + i][g * GP + r] = featin[((long)b * N_ + s.nidx[g][r]) * CIN + i];
    }
    __syncthreads();

    for (int e = t; e < G_ * CG; e += T_) {
        int g = e / CG, i = e - g * CG;
        float m = s.xsT[i][g * GP];
#pragma unroll
        for (int r = 1; r < K_; ++r) m = fmaxf(m, s.xsT[i][g * GP + r]);
        s.gmax[g][i] = m;
    }
    __syncthreads();

    for (int k = 0; k < 8; ++k) {
        const int row = w + 16 * k;
        const int g = row >> 5, r = row & 31;
        float v[5];
        int kn = 0;
        float sum = 0.f;
        for (int ii = lane; ii < CG; ii += 32) { v[kn] = s.xsT[ii][g * GP + r]; sum += v[kn]; ++kn; }
#pragma unroll
        for (int o = 16; o; o >>= 1) sum += __shfl_xor_sync(FULL, sum, o);
        const float m = sum * (1.f / CG);
        float qv = 0.f;
        for (int kk = 0; kk < kn; ++kk) { float d = v[kk] - m; qv += d * d; }
#pragma unroll
        for (int o = 16; o; o >>= 1) qv += __shfl_xor_sync(FULL, qv, o);
        const float rs = rsqrtf(qv * (1.f / CG) + 1e-3f);
        kn = 0;
        for (int ii = lane; ii < CG; ii += 32) {
            s.xsT[ii][g * GP + r] = (v[kn] - m) * rs * n1g[ii] + n1b[ii];
            ++kn;
        }
    }
    __syncthreads();

    const int gq = w & 3;
    const int mbase = 32 * gq;
    const int nbase = (w >> 2) * 64;
    const int lp = lane >> 2, lq = lane & 3;
    float cfr[2][8][4];
#pragma unroll
    for (int mt = 0; mt < 2; ++mt)
#pragma unroll
        for (int j = 0; j < 8; ++j)
#pragma unroll
            for (int e = 0; e < 4; ++e) cfr[mt][j][e] = 0.f;

    const unsigned* A0 = &s.Abf[0][0][0];
    const unsigned* A1 = &s.Abf[1][0][0];
    const unsigned* B0 = &s.Bbf[0][0][0];
    const unsigned* B1 = &s.Bbf[1][0][0];

    for (int c = 0; c < 3; ++c) {
        {
            const int mq = t & 127;
            const int qd = t >> 7;
            const int colx = (mq >> 5) * GP + (mq & 31);
#pragma unroll
            for (int jj = 0; jj < 6; ++jj) {
                const int j = qd * 6 + jj;
                const int k = c * KC + 2 * j;
                const float x0 = (k < CG) ? s.xsT[k][colx] : 0.f;
                const float x1 = (k + 1 < CG) ? s.xsT[k + 1][colx] : 0.f;
                const __nv_bfloat16 h0 = __float2bfloat16(x0), h1 = __float2bfloat16(x1);
                s.Abf[0][mq][j] = (unsigned)__bfloat16_as_ushort(h0) |
                                  ((unsigned)__bfloat16_as_ushort(h1) << 16);
                s.Abf[1][mq][j] = bf16pair(x0 - __bfloat162float(h0), x1 - __bfloat162float(h1));
            }
        }
        {
            const uint2* src = reinterpret_cast<const uint2*>(g_wq) + (long)c * 6144;
            uint2* dst = reinterpret_cast<uint2*>(&s.Bbf[0][0][0]);
            for (int i = t; i < 6144; i += T_) {
                const int row = i / 12, j2 = i % 12;
                dst[row * 13 + j2] = src[i];
            }
        }
        __syncthreads();

#pragma unroll
        for (int ks = 0; ks < 3; ++ks) {
            const int ko = ks * 8 + lq;
            unsigned ah[2][4], al[2][4];
#pragma unroll
            for (int mt = 0; mt < 2; ++mt) {
                const int r0 = (mbase + mt * 16 + lp) * AP;
                const int r8 = r0 + 8 * AP;
                ah[mt][0] = A0[r0 + ko];     ah[mt][1] = A0[r8 + ko];
                ah[mt][2] = A0[r0 + ko + 4]; ah[mt][3] = A0[r8 + ko + 4];
                al[mt][0] = A1[r0 + ko];     al[mt][1] = A1[r8 + ko];
                al[mt][2] = A1[r0 + ko + 4]; al[mt][3] = A1[r8 + ko + 4];
            }
#pragma unroll
            for (int j = 0; j < 8; ++j) {
                const int nr = (nbase + j * 8 + lp) * AP;
                const unsigned bh0 = B0[nr + ko], bh1 = B0[nr + ko + 4];
                const unsigned bl0 = B1[nr + ko], bl1 = B1[nr + ko + 4];
#pragma unroll
                for (int mt = 0; mt < 2; ++mt) {
                    mma16816(cfr[mt][j], ah[mt], bh0, bh1);
                    mma16816(cfr[mt][j], ah[mt], bl0, bl1);
                    mma16816(cfr[mt][j], al[mt], bh0, bh1);
                }
            }
        }
        __syncthreads();
    }

#pragma unroll
    for (int j = 0; j < 8; ++j) {
        float ve = fmaxf(fmaxf(cfr[0][j][0], cfr[0][j][2]), fmaxf(cfr[1][j][0], cfr[1][j][2]));
        float vo = fmaxf(fmaxf(cfr[0][j][1], cfr[0][j][3]), fmaxf(cfr[1][j][1], cfr[1][j][3]));
#pragma unroll
        for (int o = 4; o <= 16; o <<= 1) {
            ve = fmaxf(ve, __shfl_xor_sync(FULL, ve, o));
            vo = fmaxf(vo, __shfl_xor_sync(FULL, vo, o));
        }
        if (lane < 4) {
            s.qm[gq][nbase + j * 8 + 2 * lane]     = ve;
            s.qm[gq][nbase + j * 8 + 2 * lane + 1] = vo;
        }
    }
    __syncthreads();

    {
        float4 qa[G_], qb[G_];
#pragma unroll
        for (int g = 0; g < G_; ++g) {
            qa[g] = reinterpret_cast<const float4*>(s.qm[g])[lane];
            qb[g] = reinterpret_cast<const float4*>(s.qm[g])[32 + lane];
        }
        for (int i = w; i < CG; i += 16) {
            const float4* wr = reinterpret_cast<const float4*>(wqkv + (long)i * TC + C_);
            const float4 w0 = wr[lane];
            const float4 w1 = wr[32 + lane];
            float s0[G_], s1[G_];
#pragma unroll
            for (int g = 0; g < G_; ++g) {
                s0[g] = w0.x * qa[g].x + w0.y * qa[g].y + w0.z * qa[g].z + w0.w * qa[g].w;
                s1[g] = w1.x * qb[g].x + w1.y * qb[g].y + w1.z * qb[g].z + w1.w * qb[g].w;
            }
#pragma unroll
            for (int o = 8; o; o >>= 1) {
#pragma unroll
                for (int g = 0; g < G_; ++g) {
                    s0[g] += __shfl_xor_sync(FULL, s0[g], o);
                    s1[g] += __shfl_xor_sync(FULL, s1[g], o);
                }
            }
            if ((lane & 15) == 0) {
                const int h0 = lane >> 4;
#pragma unroll
                for (int g = 0; g < G_; ++g) {
                    s.z[g][h0][i]     = s0[g];
                    s.z[g][h0 + 2][i] = s1[g];
                }
            }
        }
    }
    __syncthreads();

    {
        const int g = w >> 2, h = w & 3, r = lane;
        float a = 0.f;
#pragma unroll 4
        for (int i = 0; i < CG; ++i) a += s.xsT[i][g * GP + r] * s.z[g][h][i];
        a *= 0.0625f;
        float mx = a;
#pragma unroll
        for (int o = 16; o; o >>= 1) mx = fmaxf(mx, __shfl_xor_sync(FULL, mx, o));
        const float e = expf(a - mx);
        float ss = e;
#pragma unroll
        for (int o = 16; o; o >>= 1) ss += __shfl_xor_sync(FULL, ss, o);
        s.attnw[g][h][r] = e / ss;
    }
    __syncthreads();

    for (int e = t; e < G_ * H_ * CG; e += T_) {
        const int i = e % CG;
        const int gh = e / CG;
        const int g = gh >> 2, h = gh & 3;
        const ull* aw = reinterpret_cast<const ull*>(s.attnw[g][h]);
        const ull* xr = reinterpret_cast<const ull*>(&s.xsT[i][g * GP]);
        ull acc = 0ull;
#pragma unroll
        for (int rp = 0; rp < 16; ++rp) fma2(acc, xr[rp], aw[rp]);
        float a, b2; upk2(acc, a, b2);
        s.y[g][h][i] = a + b2;
    }
    __syncthreads();

    {
        const int c = t & 255, g2 = t >> 8;
        const int h = c >> 6;
        const float* wv = wqkv + 2 * C_ + c;
        float a0 = 0.f, a1 = 0.f;
#pragma unroll 8
        for (int i = 0; i < CG; ++i) {
            const float wvi = wv[(long)i * TC];
            a0 += s.y[g2][h][i] * wvi;
            a1 += s.y[g2 + 2][h][i] * wvi;
        }
        s.sat[g2][c] = a0;
        s.sat[g2 + 2][c] = a1;
    }
    __syncthreads();

    {
        const int c = t & 255, g2 = t >> 8;
        float p0 = 0.f, p1 = 0.f;
        const float* wp = projw + c;
#pragma unroll 8
        for (int i = 0; i < C_; ++i) {
            const float wv = wp[(long)i * C_];
            p0 += s.sat[g2][i] * wv;
            p1 += s.sat[g2 + 2][i] * wv;
        }
        float d0 = 0.f, d1 = 0.f;
        const float* wd = densew + c;
#pragma unroll 8
        for (int i = 0; i < CG; ++i) {
            const float wv = wd[(long)i * C_];
            d0 += s.gmax[g2][i] * wv;
            d1 += s.gmax[g2 + 2][i] * wv;
        }
        const float pb = projb[c], db = denseb[c];
        g_feat_buf[(long)(grp0 + g2) * C_ + c]     = fmaxf(p0 + pb, 0.f) + fmaxf(d0 + db, 0.f);
        g_feat_buf[(long)(grp0 + g2 + 2) * C_ + c] = fmaxf(p1 + pb, 0.f) + fmaxf(d1 + db, 0.f);
    }
}

// ============================================================================
// K3: MLP on tensor cores. M=16 rows/block, 8 warps. fc1: warp w = cols
// w*64..+63 (j8); fc2: cols w*32..+31 (j4). K in 48-chunks, single-part B
// buffer, 2 passes/chunk (hh+lh on B_hi, hl on B_lo). LN output and fc1(relu)
// output stored directly as packed bf16 hi/lo A-operands.
// ============================================================================
struct __align__(16) SmemMlp {
    unsigned lnPk[2][MR][P1];   // fc1 A, packed bf16 pairs (19.7 KB)
    unsigned hPk[2][MR][P2];    // fc2 A (36.1 KB)
    unsigned Bbf[512][AP];      // one part of one weight chunk (53.2 KB)
};

__global__ void __launch_bounds__(256, 2) mlp_kernel(
    const float* __restrict__ fc1b, const float* __restrict__ fc2b,
    const float* __restrict__ n2g, const float* __restrict__ n2b,
    float* __restrict__ out) {
    SmemMlp& s = *reinterpret_cast<SmemMlp*>(dynsm);
    const int t = threadIdx.x;
    const int w = t >> 5, lane = t & 31;
    const int lp = lane >> 2, lq = lane & 3;
    const long row0 = (long)blockIdx.x * MR;

    // zero K-tail pads (fc1 frags reach words 128..143; fc2 reach 256..263)
    for (int i = t; i < 512; i += 256) {
        const int part = i >> 8, rr = (i >> 4) & 15, wd = i & 15;
        s.lnPk[part][rr][128 + wd] = 0u;
    }
    if (t < 256) {
        const int part = t >> 7, rr = (t >> 3) & 15, wd = t & 7;
        s.hPk[part][rr][256 + wd] = 0u;
    }

    // LN: 16 rows, warp w handles rows w and w+8; lane owns col-pairs
    for (int rr = 0; rr < 2; ++rr) {
        const int r = w + 8 * rr;
        const float2* frow = reinterpret_cast<const float2*>(g_feat_buf + (row0 + r) * C_);
        float2 v[4];
        float sum = 0.f;
#pragma unroll
        for (int k = 0; k < 4; ++k) { v[k] = frow[lane + 32 * k]; sum += v[k].x + v[k].y; }
#pragma unroll
        for (int o = 16; o; o >>= 1) sum += __shfl_xor_sync(FULL, sum, o);
        const float m = sum * (1.f / C_);
        float qv = 0.f;
#pragma unroll
        for (int k = 0; k < 4; ++k) {
            const float dx = v[k].x - m, dy = v[k].y - m;
            qv += dx * dx + dy * dy;
        }
#pragma unroll
        for (int o = 16; o; o >>= 1) qv += __shfl_xor_sync(FULL, qv, o);
        const float rs = rsqrtf(qv * (1.f / C_) + 1e-3f);
#pragma unroll
        for (int k = 0; k < 4; ++k) {
            const int wi = lane + 32 * k;
            const float2 gg = reinterpret_cast<const float2*>(n2g)[wi];
            const float2 bb = reinterpret_cast<const float2*>(n2b)[wi];
            const float x0 = (v[k].x - m) * rs * gg.x + bb.x;
            const float x1 = (v[k].y - m) * rs * gg.y + bb.y;
            const __nv_bfloat16 h0 = __float2bfloat16(x0), h1 = __float2bfloat16(x1);
            s.lnPk[0][r][wi] = (unsigned)__bfloat16_as_ushort(h0) |
                               ((unsigned)__bfloat16_as_ushort(h1) << 16);
            s.lnPk[1][r][wi] = bf16pair(x0 - __bfloat162float(h0), x1 - __bfloat162float(h1));
        }
    }
    __syncthreads();

    const unsigned* BB = &s.Bbf[0][0];

    // ================= fc1: N=512, K=256 (6 chunks) =================
    float cfr[8][4];
#pragma unroll
    for (int j = 0; j < 8; ++j)
#pragma unroll
        for (int e = 0; e < 4; ++e) cfr[j][e] = 0.f;
    {
        const unsigned* A0 = &s.lnPk[0][0][0];
        const unsigned* A1 = &s.lnPk[1][0][0];
        for (int c = 0; c < 6; ++c) {
            {   // B hi
                const uint2* src = reinterpret_cast<const uint2*>(g_w1) + (long)(c * 2) * 6144;
                uint2* dst = reinterpret_cast<uint2*>(&s.Bbf[0][0]);
                for (int i = t; i < 6144; i += 256) {
                    const int row = i / 12, j2 = i % 12;
                    dst[row * 13 + j2] = src[i];
                }
            }
            __syncthreads();
#pragma unroll
            for (int ks = 0; ks < 3; ++ks) {
                const int ko = c * 24 + ks * 8 + lq;
                const int kb = ks * 8 + lq;
                unsigned ah[4], al[4];
                ah[0] = A0[lp * P1 + ko];           ah[1] = A0[(lp + 8) * P1 + ko];
                ah[2] = A0[lp * P1 + ko + 4];       ah[3] = A0[(lp + 8) * P1 + ko + 4];
                al[0] = A1[lp * P1 + ko];           al[1] = A1[(lp + 8) * P1 + ko];
                al[2] = A1[lp * P1 + ko + 4];       al[3] = A1[(lp + 8) * P1 + ko + 4];
#pragma unroll
                for (int j = 0; j < 8; ++j) {
                    const int nr = (w * 64 + j * 8 + lp) * AP;
                    const unsigned b0 = BB[nr + kb], b1 = BB[nr + kb + 4];
                    mma16816(cfr[j], ah, b0, b1);
                    mma16816(cfr[j], al, b0, b1);
                }
            }
            __syncthreads();
            {   // B lo
                const uint2* src = reinterpret_cast<const uint2*>(g_w1) + (long)(c * 2 + 1) * 6144;
                uint2* dst = reinterpret_cast<uint2*>(&s.Bbf[0][0]);
                for (int i = t; i < 6144; i += 256) {
                    const int row = i / 12, j2 = i % 12;
                    dst[row * 13 + j2] = src[i];
                }
            }
            __syncthreads();
#pragma unroll
            for (int ks = 0; ks < 3; ++ks) {
                const int ko = c * 24 + ks * 8 + lq;
                const int kb = ks * 8 + lq;
                unsigned ah[4];
                ah[0] = A0[lp * P1 + ko];           ah[1] = A0[(lp + 8) * P1 + ko];
                ah[2] = A0[lp * P1 + ko + 4];       ah[3] = A0[(lp + 8) * P1 + ko + 4];
#pragma unroll
                for (int j = 0; j < 8; ++j) {
                    const int nr = (w * 64 + j * 8 + lp) * AP;
                    const unsigned b0 = BB[nr + kb], b1 = BB[nr + kb + 4];
                    mma16816(cfr[j], ah, b0, b1);
                }
            }
            __syncthreads();
        }
    }

    // fc1 epilogue: bias + relu -> hPk (packed bf16 hi/lo)
#pragma unroll
    for (int j = 0; j < 8; ++j) {
        const float2 bj = *reinterpret_cast<const float2*>(fc1b + w * 64 + j * 8 + 2 * lq);
        const int wd = w * 32 + j * 4 + lq;
        {
            const float v0 = fmaxf(cfr[j][0] + bj.x, 0.f);
            const float v1 = fmaxf(cfr[j][1] + bj.y, 0.f);
            const __nv_bfloat16 h0 = __float2bfloat16(v0), h1 = __float2bfloat16(v1);
            s.hPk[0][lp][wd] = (unsigned)__bfloat16_as_ushort(h0) |
                               ((unsigned)__bfloat16_as_ushort(h1) << 16);
            s.hPk[1][lp][wd] = bf16pair(v0 - __bfloat162float(h0), v1 - __bfloat162float(h1));
        }
        {
            const float v0 = fmaxf(cfr[j][2] + bj.x, 0.f);
            const float v1 = fmaxf(cfr[j][3] + bj.y, 0.f);
            const __nv_bfloat16 h0 = __float2bfloat16(v0), h1 = __float2bfloat16(v1);
            s.hPk[0][lp + 8][wd] = (unsigned)__bfloat16_as_ushort(h0) |
                                   ((unsigned)__bfloat16_as_ushort(h1) << 16);
            s.hPk[1][lp + 8][wd] = bf16pair(v0 - __bfloat162float(h0), v1 - __bfloat162float(h1));
        }
    }
    __syncthreads();

    // ================= fc2: N=256, K=512 (11 chunks) =================
    float c2[4][4];
#pragma unroll
    for (int j = 0; j < 4; ++j)
#pragma unroll
        for (int e = 0; e < 4; ++e) c2[j][e] = 0.f;
    {
        const unsigned* H0 = &s.hPk[0][0][0];
        const unsigned* H1 = &s.hPk[1][0][0];
        for (int c = 0; c < 11; ++c) {
            {   // B hi
                const uint2* src = reinterpret_cast<const uint2*>(g_w2) + (long)(c * 2) * 3072;
                uint2* dst = reinterpret_cast<uint2*>(&s.Bbf[0][0]);
                for (int i = t; i < 3072; i += 256) {
                    const int row = i / 12, j2 = i % 12;
                    dst[row * 13 + j2] = src[i];
                }
            }
            __syncthreads();
#pragma unroll
            for (int ks = 0; ks < 3; ++ks) {
                const int ko = c * 24 + ks * 8 + lq;
                const int kb = ks * 8 + lq;
                unsigned ah[4], al[4];
                ah[0] = H0[lp * P2 + ko];           ah[1] = H0[(lp + 8) * P2 + ko];
                ah[2] = H0[lp * P2 + ko + 4];       ah[3] = H0[(lp + 8) * P2 + ko + 4];
                al[0] = H1[lp * P2 + ko];           al[1] = H1[(lp + 8) * P2 + ko];
                al[2] = H1[lp * P2 + ko + 4];       al[3] = H1[(lp + 8) * P2 + ko + 4];
#pragma unroll
                for (int j = 0; j < 4; ++j) {
                    const int nr = (w * 32 + j * 8 + lp) * AP;
                    const unsigned b0 = BB[nr + kb], b1 = BB[nr + kb + 4];
                    mma16816(c2[j], ah, b0, b1);
                    mma16816(c2[j], al, b0, b1);
                }
            }
            __syncthreads();
            {   // B lo
                const uint2* src = reinterpret_cast<const uint2*>(g_w2) + (long)(c * 2 + 1) * 3072;
                uint2* dst = reinterpret_cast<uint2*>(&s.Bbf[0][0]);
                for (int i = t; i < 3072; i += 256) {
                    const int row = i / 12, j2 = i % 12;
                    dst[row * 13 + j2] = src[i];
                }
            }
            __syncthreads();
#pragma unroll
            for (int ks = 0; ks < 3; ++ks) {
                const int ko = c * 24 + ks * 8 + lq;
                const int kb = ks * 8 + lq;
                unsigned ah[4];
                ah[0] = H0[lp * P2 + ko];           ah[1] = H0[(lp + 8) * P2 + ko];
                ah[2] = H0[lp * P2 + ko + 4];       ah[3] = H0[(lp + 8) * P2 + ko + 4];
#pragma unroll
                for (int j = 0; j < 4; ++j) {
                    const int nr = (w * 32 + j * 8 + lp) * AP;
                    const unsigned b0 = BB[nr + kb], b1 = BB[nr + kb + 4];
                    mma16816(c2[j], ah, b0, b1);
                }
            }
            __syncthreads();
        }
    }

    // fc2 epilogue: bias + residual + store
#pragma unroll
    for (int j = 0; j < 4; ++j) {
        const int col = w * 32 + j * 8 + 2 * lq;
        const float2 bj = *reinterpret_cast<const float2*>(fc2b + col);
        {
            const long row = row0 + lp;
            const float2 res = *reinterpret_cast<const float2*>(g_feat_buf + row * C_ + col);
            float2 o;
            o.x = c2[j][0] + bj.x + res.x;
            o.y = c2[j][1] + bj.y + res.y;
            *reinterpret_cast<float2*>(out + row * C_ + col) = o;
        }
        {
            const long row = row0 + lp + 8;
            const float2 res = *reinterpret_cast<const float2*>(g_feat_buf + row * C_ + col);
            float2 o;
            o.x = c2[j][2] + bj.x + res.x;
            o.y = c2[j][3] + bj.y + res.y;
            *reinterpret_cast<float2*>(out + row * C_ + col) = o;
        }
    }
}

// ============================================================================
extern "C" void kernel_launch(void* const* d_in, const int* in_sizes, int n_in,
                              void* d_out, int out_size) {
    const float* xyz    = (const float*)d_in[0];
    const float* nxyz   = (const float*)d_in[1];
    const float* featin = (const float*)d_in[2];
    const float* wqkv   = (const float*)d_in[3];
    const float* projw  = (const float*)d_in[4];
    const float* projb  = (const float*)d_in[5];
    const float* densew = (const float*)d_in[6];
    const float* denseb = (const float*)d_in[7];
    const float* fc1w   = (const float*)d_in[8];
    const float* fc1b   = (const float*)d_in[9];
    const float* fc2w   = (const float*)d_in[10];
    const float* fc2b   = (const float*)d_in[11];
    const float* n1g    = (const float*)d_in[12];
    const float* n1b    = (const float*)d_in[13];
    const float* n2g    = (const float*)d_in[14];
    const float* n2b    = (const float*)d_in[15];
    float* out = (float*)d_out;

    (void)in_sizes; (void)n_in; (void)out_size;

    const int knn_smem  = N_ * (int)sizeof(float4);            // 64 KB
    const int attn_smem = (int)sizeof(SmemAll);                // ~178 KB
    const int mlp_smem  = (int)sizeof(SmemMlp);                // ~109 KB
    cudaFuncSetAttribute(knn_kernel, cudaFuncAttributeMaxDynamicSharedMemorySize, knn_smem);
    cudaFuncSetAttribute(attn_kernel, cudaFuncAttributeMaxDynamicSharedMemorySize, attn_smem);
    cudaFuncSetAttribute(mlp_kernel, cudaFuncAttributeMaxDynamicSharedMemorySize, mlp_smem);

    prep_kernel<<<312, 512>>>(wqkv, fc1w, fc2w);
    knn_kernel<<<dim3(NP_ / 8, B_), 256, knn_smem>>>(xyz, nxyz);
    attn_kernel<<<B_ * NP_ / G_, T_, attn_smem>>>(xyz, nxyz, featin, wqkv, projw, projb,
                                                  densew, denseb, n1g, n1b);
    mlp_kernel<<<B_ * NP_ / MR, 256, mlp_smem>>>(fc1b, fc2b, n2g, n2b, out);
}